// round 9
// baseline (speedup 1.0000x reference)
#include <cuda_runtime.h>
#include <cuda_fp16.h>
#include <math.h>
#include <stdint.h>

#define EPSF 1e-6f

// Problem constants: B=4, S=1024, D=1024, H=16, DH=64, F=4096, M=B*S=4096
__device__ float g_xn  [4096 * 1024 / 2];    // xn (half)
__device__ float g_qkv [6 * 1024 * 1024];    // q|k|v (half, 3 x 4M halves); v->attn_out
__device__ float g_res [4096 * 1024];        // residual after attention (f32)
__device__ float g_big [16 * 1024 * 1024];   // h1/h2 (half, 2 x 16M halves)
__device__ float g_wt  [8 * 1024 * 1024];    // transposed half weights (16M halves)
__device__ float g_vt  [2 * 1024 * 1024];    // vt (half) [b][d][s]
__device__ float g_bias[16384];              // b_qkv (3072) @0, b12 (8192) @4096

// ---------------------------------------------------------------------------
// Helpers
// ---------------------------------------------------------------------------
__device__ __forceinline__ void cp_async16(uint32_t dst, const void* src)
{
    asm volatile("cp.async.cg.shared.global [%0], [%1], 16;\n" :: "r"(dst), "l"(src));
}
__device__ __forceinline__ void cp_commit() { asm volatile("cp.async.commit_group;\n"); }
__device__ __forceinline__ void cp_wait0()  { asm volatile("cp.async.wait_group 0;\n"); }

__device__ __forceinline__ uint32_t smem_u32(const void* p)
{
    uint32_t a;
    asm("{ .reg .u64 t; cvta.to.shared.u64 t, %1; cvt.u32.u64 %0, t; }" : "=r"(a) : "l"(p));
    return a;
}
__device__ __forceinline__ void ldsm4(uint32_t& r0, uint32_t& r1, uint32_t& r2, uint32_t& r3,
                                      uint32_t a)
{
    asm volatile("ldmatrix.sync.aligned.m8n8.x4.shared.b16 {%0,%1,%2,%3}, [%4];"
                 : "=r"(r0), "=r"(r1), "=r"(r2), "=r"(r3) : "r"(a));
}
__device__ __forceinline__ void mma_h(float c[4], const uint32_t a[4], const uint32_t b[2])
{
    asm volatile(
        "mma.sync.aligned.m16n8k16.row.col.f32.f16.f16.f32 "
        "{%0,%1,%2,%3}, {%4,%5,%6,%7}, {%8,%9}, {%0,%1,%2,%3};\n"
        : "+f"(c[0]), "+f"(c[1]), "+f"(c[2]), "+f"(c[3])
        : "r"(a[0]), "r"(a[1]), "r"(a[2]), "r"(a[3]), "r"(b[0]), "r"(b[1]));
}

// ---------------------------------------------------------------------------
// fp16 tensor-core GEMM, BM=256 BN=128 BK=32, 8 warps as 4(m) x 2(n),
// warp tile 64x64. Double-buffered cp.async (round-6 discipline: wait0).
// Smem row stride 40 halves -> conflict-free ldmatrix.
// MODE 0: half out, segmented columns (fused QKV / fused FFN).
// MODE 1: float out = acc + bias + Res (ldc = segStride).
// ---------------------------------------------------------------------------
#define GE_A_STAGE (256 * 40 * 2)    // 20480 B
#define GE_B_STAGE (128 * 40 * 2)    // 10240 B
#define GE_SMEM (2 * (GE_A_STAGE + GE_B_STAGE))   // 61440 B

template <int MODE>
__global__ __launch_bounds__(256, 1) void gemm_h(
    const __half* __restrict__ A, const __half* __restrict__ B,
    const float* __restrict__ bias, const float* __restrict__ Res,
    void* __restrict__ Cv, int K, int lda, int ldb, int segW, int segStride)
{
    extern __shared__ __half gsm[];
    const uint32_t sA = smem_u32(gsm);
    const uint32_t sB = sA + 2 * GE_A_STAGE;

    const int t    = threadIdx.x;
    const int lane = t & 31;
    const int warp = t >> 5;
    const size_t m0 = (size_t)blockIdx.y * 256;
    const size_t n0 = (size_t)blockIdx.x * 128;
    const int wm = (warp >> 1) * 64;
    const int wn = (warp & 1) * 64;

    // cp.async maps: A 256x32 halves (4 chunks/thread), B 128x32 (2 chunks/thread)
    uint32_t dA[4], dB[2];
    const __half* aS[4];
    const __half* bS[2];
    #pragma unroll
    for (int i = 0; i < 4; i++) {
        const int idx = t + 256 * i;
        const int row = idx >> 2, c = idx & 3;
        dA[i] = (uint32_t)(row * 40 + c * 8) * 2;
        aS[i] = A + (m0 + row) * lda + c * 8;
    }
    #pragma unroll
    for (int i = 0; i < 2; i++) {
        const int idx = t + 256 * i;
        const int row = idx >> 2, c = idx & 3;
        dB[i] = (uint32_t)(row * 40 + c * 8) * 2;
        bS[i] = B + (n0 + row) * ldb + c * 8;
    }

    const int lq = lane >> 3, lr = lane & 7;
    uint32_t aAddr[4], bAddr[4];
    #pragma unroll
    for (int mt = 0; mt < 4; mt++)
        aAddr[mt] = sA + (uint32_t)((wm + mt * 16 + ((lq & 1) << 3) + lr) * 40 + ((lq >> 1) << 3)) * 2;
    #pragma unroll
    for (int p = 0; p < 4; p++)
        bAddr[p] = sB + (uint32_t)((wn + p * 16 + ((lq >> 1) << 3) + lr) * 40 + ((lq & 1) << 3)) * 2;

    float acc[4][8][4];
    #pragma unroll
    for (int mt = 0; mt < 4; mt++)
        #pragma unroll
        for (int nt = 0; nt < 8; nt++)
            #pragma unroll
            for (int i = 0; i < 4; i++) acc[mt][nt][i] = 0.f;

    // preload stage 0
    #pragma unroll
    for (int i = 0; i < 4; i++) cp_async16(sA + dA[i], aS[i]);
    #pragma unroll
    for (int i = 0; i < 2; i++) cp_async16(sB + dB[i], bS[i]);
    cp_commit();

    const int nIter = K >> 5;
    for (int it = 0; it < nIter; ++it) {
        cp_wait0();
        __syncthreads();
        const int buf = it & 1;
        if (it + 1 < nIter) {
            const int k0 = (it + 1) << 5;
            const uint32_t offA = (buf ^ 1) * GE_A_STAGE;
            const uint32_t offB = (buf ^ 1) * GE_B_STAGE;
            #pragma unroll
            for (int i = 0; i < 4; i++) cp_async16(sA + offA + dA[i], aS[i] + k0);
            #pragma unroll
            for (int i = 0; i < 2; i++) cp_async16(sB + offB + dB[i], bS[i] + k0);
            cp_commit();
        }
        const uint32_t offA = buf * GE_A_STAGE;
        const uint32_t offB = buf * GE_B_STAGE;
        #pragma unroll
        for (int ks = 0; ks < 2; ks++) {
            const uint32_t kB = ks * 32;   // 16 halves
            uint32_t af[4][4];
            #pragma unroll
            for (int mt = 0; mt < 4; mt++)
                ldsm4(af[mt][0], af[mt][1], af[mt][2], af[mt][3], aAddr[mt] + offA + kB);
            uint32_t bf[8][2];
            #pragma unroll
            for (int p = 0; p < 4; p++)
                ldsm4(bf[2 * p][0], bf[2 * p][1], bf[2 * p + 1][0], bf[2 * p + 1][1],
                      bAddr[p] + offB + kB);
            #pragma unroll
            for (int mt = 0; mt < 4; mt++)
                #pragma unroll
                for (int nt = 0; nt < 8; nt++)
                    mma_h(acc[mt][nt], af[mt], bf[nt]);
        }
        __syncthreads();
    }

    // Epilogue
    if (MODE == 0) {
        const int seg  = (int)(n0 / segW);
        const int ncol = (int)(n0 % segW);
        __half* Cb = (__half*)Cv + (size_t)seg * segStride + m0 * segW + ncol;
        #pragma unroll
        for (int mt = 0; mt < 4; mt++) {
            const int r0 = wm + mt * 16 + (lane >> 2);
            #pragma unroll
            for (int nt = 0; nt < 8; nt++) {
                const int c = wn + nt * 8 + (lane & 3) * 2;
                const float b0 = bias[n0 + c], b1 = bias[n0 + c + 1];
                *(__half2*)(Cb + (size_t)r0 * segW + c) =
                    __floats2half2_rn(acc[mt][nt][0] + b0, acc[mt][nt][1] + b1);
                *(__half2*)(Cb + (size_t)(r0 + 8) * segW + c) =
                    __floats2half2_rn(acc[mt][nt][2] + b0, acc[mt][nt][3] + b1);
            }
        }
    } else {
        const int ldc = segStride;
        float* Cb = (float*)Cv + m0 * ldc + n0;
        const float* Rb = Res + m0 * ldc + n0;
        #pragma unroll
        for (int mt = 0; mt < 4; mt++) {
            const int r0 = wm + mt * 16 + (lane >> 2);
            #pragma unroll
            for (int nt = 0; nt < 8; nt++) {
                const int c = wn + nt * 8 + (lane & 3) * 2;
                const float b0 = bias[n0 + c], b1 = bias[n0 + c + 1];
                float2 ra = *(const float2*)(Rb + (size_t)r0 * ldc + c);
                float2 rb = *(const float2*)(Rb + (size_t)(r0 + 8) * ldc + c);
                *(float2*)(Cb + (size_t)r0 * ldc + c) =
                    make_float2(acc[mt][nt][0] + b0 + ra.x, acc[mt][nt][1] + b1 + ra.y);
                *(float2*)(Cb + (size_t)(r0 + 8) * ldc + c) =
                    make_float2(acc[mt][nt][2] + b0 + rb.x, acc[mt][nt][3] + b1 + rb.y);
            }
        }
    }
}

// ---------------------------------------------------------------------------
// Bias concat: b_qkv = bq|bk|bv at g_bias[0..3072); b12 = b1|b2 at [4096..12288)
// ---------------------------------------------------------------------------
__global__ __launch_bounds__(256) void concat_bias(
    float* __restrict__ dst, const float* __restrict__ bq, const float* __restrict__ bk,
    const float* __restrict__ bv, const float* __restrict__ b1, const float* __restrict__ b2)
{
    const int i = blockIdx.x * 256 + threadIdx.x;
    if (i < 1024)       dst[i] = bq[i];
    else if (i < 2048)  dst[i] = bk[i - 1024];
    else if (i < 3072)  dst[i] = bv[i - 2048];
    else if (i < 3072 + 4096)  dst[1024 + i] = b1[i - 3072];
    else if (i < 3072 + 8192)  dst[1024 + i] = b2[i - 7168];
}

// ---------------------------------------------------------------------------
// Batched transpose f32 -> half: 4 independent sources, z selects source.
// ---------------------------------------------------------------------------
__global__ __launch_bounds__(256) void trans_f2h4(
    const float* __restrict__ i0, const float* __restrict__ i1,
    const float* __restrict__ i2, const float* __restrict__ i3,
    __half* __restrict__ o0, __half* __restrict__ o1,
    __half* __restrict__ o2, __half* __restrict__ o3, int R, int C)
{
    __shared__ float tile[32][33];
    const float* in;
    __half* out;
    switch (blockIdx.z) {
        case 0: in = i0; out = o0; break;
        case 1: in = i1; out = o1; break;
        case 2: in = i2; out = o2; break;
        default: in = i3; out = o3; break;
    }
    const int c0 = blockIdx.x * 32, r0 = blockIdx.y * 32;
    const int tx = threadIdx.x & 31, ty = threadIdx.x >> 5;
    #pragma unroll
    for (int i = 0; i < 4; i++)
        tile[ty + 8 * i][tx] = in[(size_t)(r0 + ty + 8 * i) * C + c0 + tx];
    __syncthreads();
    #pragma unroll
    for (int i = 0; i < 4; i++)
        out[(size_t)(c0 + ty + 8 * i) * R + r0 + tx] = __float2half_rn(tile[tx][ty + 8 * i]);
}

// ---------------------------------------------------------------------------
// Transpose half -> half (batched over z): in[R][C] -> out[C][R]
// ---------------------------------------------------------------------------
__global__ __launch_bounds__(256) void trans_h2h(
    const __half* __restrict__ in, __half* __restrict__ out, int R, int C)
{
    __shared__ __half tile[32][34];
    const size_t zoff = (size_t)blockIdx.z * R * C;
    in += zoff; out += zoff;
    const int c0 = blockIdx.x * 32, r0 = blockIdx.y * 32;
    const int tx = threadIdx.x & 31, ty = threadIdx.x >> 5;
    #pragma unroll
    for (int i = 0; i < 4; i++)
        tile[ty + 8 * i][tx] = in[(size_t)(r0 + ty + 8 * i) * C + c0 + tx];
    __syncthreads();
    #pragma unroll
    for (int i = 0; i < 4; i++)
        out[(size_t)(c0 + ty + 8 * i) * R + r0 + tx] = tile[tx][ty + 8 * i];
}

// ---------------------------------------------------------------------------
// Flash attention fp16 (proven round-6 version).
// ---------------------------------------------------------------------------
#define FL_SMEM ((128 * 72 + 64 * 136 + 128 * 136) * 2)

__global__ __launch_bounds__(256) void flash_h(
    const __half* __restrict__ q, const __half* __restrict__ k,
    const __half* __restrict__ vt, __half* __restrict__ out)
{
    extern __shared__ __half smh[];
    const uint32_t sK = smem_u32(smh);
    const uint32_t sV = sK + 128 * 72 * 2;
    const uint32_t sP = sV + 64 * 136 * 2;
    __half* sPh = smh + 128 * 72 + 64 * 136;

    const int t = threadIdx.x;
    const int lane = t & 31, warp = t >> 5;
    const int lq = lane >> 3, lr = lane & 7;
    const int bh = blockIdx.y, b = bh >> 4, h = bh & 15;
    const int q0 = blockIdx.x * 128;
    const int wm = warp * 16;

    const __half* qb = q + ((size_t)b * 1024 + q0) * 1024 + h * 64;
    const __half* kb = k + ((size_t)b << 20) + h * 64;
    const __half* vb = vt + ((size_t)b << 20) + (size_t)h * 64 * 1024;

    {
        #pragma unroll
        for (int i = 0; i < 4; i++) {
            const int idx = t + 256 * i;
            const int row = idx >> 3, c = idx & 7;
            cp_async16(sP + (uint32_t)(row * 72 + c * 8) * 2, qb + (size_t)row * 1024 + c * 8);
        }
    }
    cp_commit(); cp_wait0(); __syncthreads();

    uint32_t qf[4][4];
    {
        const uint32_t a0 = sP + (uint32_t)((wm + ((lq & 1) << 3) + lr) * 72 + ((lq >> 1) << 3)) * 2;
        #pragma unroll
        for (int ks = 0; ks < 4; ks++)
            ldsm4(qf[ks][0], qf[ks][1], qf[ks][2], qf[ks][3], a0 + ks * 32);
    }
    __syncthreads();

    float o[8][4];
    #pragma unroll
    for (int i = 0; i < 8; i++)
        #pragma unroll
        for (int j = 0; j < 4; j++) o[i][j] = 0.f;
    float m0 = -1e30f, m1 = -1e30f, l0 = 0.f, l1 = 0.f;

    const uint32_t aP = sP + (uint32_t)((wm + ((lq & 1) << 3) + lr) * 136 + ((lq >> 1) << 3)) * 2;

    for (int it = 0; it < 8; ++it) {
        const int kt0 = it * 128;
        #pragma unroll
        for (int i = 0; i < 4; i++) {
            const int idx = t + 256 * i;
            const int row = idx >> 3, c = idx & 7;
            cp_async16(sK + (uint32_t)(row * 72 + c * 8) * 2,
                       kb + (size_t)(kt0 + row) * 1024 + c * 8);
        }
        #pragma unroll
        for (int i = 0; i < 4; i++) {
            const int idx = t + 256 * i;
            const int row = idx >> 4, c = idx & 15;
            cp_async16(sV + (uint32_t)(row * 136 + c * 8) * 2,
                       vb + (size_t)row * 1024 + kt0 + c * 8);
        }
        cp_commit(); cp_wait0(); __syncthreads();

        float s[16][4];
        #pragma unroll
        for (int i = 0; i < 16; i++)
            #pragma unroll
            for (int j = 0; j < 4; j++) s[i][j] = 0.f;
        #pragma unroll
        for (int ks = 0; ks < 4; ks++) {
            uint32_t bf[16][2];
            #pragma unroll
            for (int p = 0; p < 8; p++) {
                const uint32_t addr =
                    sK + (uint32_t)((p * 16 + ((lq >> 1) << 3) + lr) * 72 + ((lq & 1) << 3)) * 2
                       + ks * 32;
                ldsm4(bf[2 * p][0], bf[2 * p][1], bf[2 * p + 1][0], bf[2 * p + 1][1], addr);
            }
            #pragma unroll
            for (int nt = 0; nt < 16; nt++)
                mma_h(s[nt], qf[ks], bf[nt]);
        }

        float c0v = -1e30f, c1v = -1e30f;
        #pragma unroll
        for (int nt = 0; nt < 16; nt++) {
            c0v = fmaxf(c0v, fmaxf(s[nt][0], s[nt][1]));
            c1v = fmaxf(c1v, fmaxf(s[nt][2], s[nt][3]));
        }
        c0v = fmaxf(c0v, __shfl_xor_sync(0xffffffffu, c0v, 1));
        c0v = fmaxf(c0v, __shfl_xor_sync(0xffffffffu, c0v, 2));
        c1v = fmaxf(c1v, __shfl_xor_sync(0xffffffffu, c1v, 1));
        c1v = fmaxf(c1v, __shfl_xor_sync(0xffffffffu, c1v, 2));
        const float m0n = fmaxf(m0, c0v * 0.125f);
        const float m1n = fmaxf(m1, c1v * 0.125f);
        const float cor0 = __expf(m0 - m0n);
        const float cor1 = __expf(m1 - m1n);
        m0 = m0n; m1 = m1n;
        float sum0 = 0.f, sum1 = 0.f;
        {
            __half* pr0 = sPh + (size_t)(wm + (lane >> 2)) * 136 + 2 * (lane & 3);
            __half* pr1 = pr0 + 8 * 136;
            #pragma unroll
            for (int nt = 0; nt < 16; nt++) {
                float p0 = __expf(fmaf(0.125f, s[nt][0], -m0n));
                float p1 = __expf(fmaf(0.125f, s[nt][1], -m0n));
                float p2 = __expf(fmaf(0.125f, s[nt][2], -m1n));
                float p3 = __expf(fmaf(0.125f, s[nt][3], -m1n));
                sum0 += p0 + p1; sum1 += p2 + p3;
                *(__half2*)(pr0 + nt * 8) = __floats2half2_rn(p0, p1);
                *(__half2*)(pr1 + nt * 8) = __floats2half2_rn(p2, p3);
            }
        }
        sum0 += __shfl_xor_sync(0xffffffffu, sum0, 1);
        sum0 += __shfl_xor_sync(0xffffffffu, sum0, 2);
        sum1 += __shfl_xor_sync(0xffffffffu, sum1, 1);
        sum1 += __shfl_xor_sync(0xffffffffu, sum1, 2);
        l0 = l0 * cor0 + sum0;
        l1 = l1 * cor1 + sum1;
        #pragma unroll
        for (int nt = 0; nt < 8; nt++) {
            o[nt][0] *= cor0; o[nt][1] *= cor0;
            o[nt][2] *= cor1; o[nt][3] *= cor1;
        }
        __syncwarp();

        #pragma unroll
        for (int ks2 = 0; ks2 < 8; ks2++) {
            uint32_t af[4];
            ldsm4(af[0], af[1], af[2], af[3], aP + ks2 * 32);
            uint32_t bf2[8][2];
            #pragma unroll
            for (int p = 0; p < 4; p++) {
                const uint32_t addr =
                    sV + (uint32_t)((p * 16 + ((lq >> 1) << 3) + lr) * 136 + ((lq & 1) << 3)) * 2
                       + ks2 * 32;
                ldsm4(bf2[2 * p][0], bf2[2 * p][1], bf2[2 * p + 1][0], bf2[2 * p + 1][1], addr);
            }
            #pragma unroll
            for (int nt = 0; nt < 8; nt++)
                mma_h(o[nt], af, bf2[nt]);
        }
        __syncthreads();
    }

    const float inv0 = 1.f / l0, inv1 = 1.f / l1;
    __half* ob = out + ((size_t)b * 1024 + q0 + wm + (lane >> 2)) * 1024 + h * 64 + 2 * (lane & 3);
    #pragma unroll
    for (int nt = 0; nt < 8; nt++) {
        *(__half2*)(ob + nt * 8) = __floats2half2_rn(o[nt][0] * inv0, o[nt][1] * inv0);
        *(__half2*)(ob + 8 * 1024 + nt * 8) = __floats2half2_rn(o[nt][2] * inv1, o[nt][3] * inv1);
    }
}

// ---------------------------------------------------------------------------
// LayerNorm over D=1024, f32 in -> half out.
// ---------------------------------------------------------------------------
__global__ __launch_bounds__(256) void ln_kernel(
    const float* __restrict__ in, const float* __restrict__ sc,
    const float* __restrict__ bi, __half* __restrict__ out)
{
    const int row = blockIdx.x;
    const int t = threadIdx.x;
    const float4* x4 = (const float4*)(in + (size_t)row * 1024);
    float4 v = x4[t];
    float s  = v.x + v.y + v.z + v.w;
    float ss = v.x * v.x + v.y * v.y + v.z * v.z + v.w * v.w;
    #pragma unroll
    for (int o = 16; o; o >>= 1) {
        s  += __shfl_xor_sync(0xffffffffu, s,  o);
        ss += __shfl_xor_sync(0xffffffffu, ss, o);
    }
    __shared__ float sred[8], ssred[8];
    if ((t & 31) == 0) { sred[t >> 5] = s; ssred[t >> 5] = ss; }
    __syncthreads();
    float tot = 0.f, tots = 0.f;
    #pragma unroll
    for (int w = 0; w < 8; w++) { tot += sred[w]; tots += ssred[w]; }
    const float mean = tot * (1.f / 1024.f);
    const float var  = tots * (1.f / 1024.f) - mean * mean;
    const float inv  = rsqrtf(var + EPSF);
    float4 sv = ((const float4*)sc)[t];
    float4 bv = ((const float4*)bi)[t];
    __half2* o2 = (__half2*)(out + (size_t)row * 1024);
    o2[t * 2 + 0] = __floats2half2_rn((v.x - mean) * inv * sv.x + bv.x,
                                      (v.y - mean) * inv * sv.y + bv.y);
    o2[t * 2 + 1] = __floats2half2_rn((v.z - mean) * inv * sv.z + bv.z,
                                      (v.w - mean) * inv * sv.w + bv.w);
}

// ---------------------------------------------------------------------------
// QK-norm over DH=64 with (H,DH) f32 scale/bias; half in-place.
// ---------------------------------------------------------------------------
__global__ __launch_bounds__(256) void qknorm_kernel(
    __half* __restrict__ q, const float* __restrict__ sc, const float* __restrict__ bi)
{
    const int gw   = (blockIdx.x * 256 + threadIdx.x) >> 5;
    const int lane = threadIdx.x & 31;
    const int h  = gw & 15;
    const int bs = gw >> 4;
    __half2* p = (__half2*)(q + (size_t)bs * 1024 + h * 64) + lane;
    float2 v = __half22float2(*p);
    float s  = v.x + v.y;
    float ss = v.x * v.x + v.y * v.y;
    #pragma unroll
    for (int o = 16; o; o >>= 1) {
        s  += __shfl_xor_sync(0xffffffffu, s,  o);
        ss += __shfl_xor_sync(0xffffffffu, ss, o);
    }
    const float mean = s * (1.f / 64.f);
    const float var  = ss * (1.f / 64.f) - mean * mean;
    const float inv  = rsqrtf(var + EPSF);
    const float* scp = sc + h * 64 + lane * 2;
    const float* bip = bi + h * 64 + lane * 2;
    *p = __floats2half2_rn((v.x - mean) * inv * scp[0] + bip[0],
                           (v.y - mean) * inv * scp[1] + bip[1]);
}

// ---------------------------------------------------------------------------
// GeGLU: h1 <- h1 * gelu_tanh(h2), half, 4 halves/thread.
// ---------------------------------------------------------------------------
__device__ __forceinline__ float gelu_t(float x)
{
    return 0.5f * x * (1.f + tanhf(0.7978845608028654f * (x + 0.044715f * x * x * x)));
}

__global__ __launch_bounds__(256) void geglu_kernel(
    __half* __restrict__ g1, const __half* __restrict__ g2)
{
    const size_t i = (size_t)blockIdx.x * 256 + threadIdx.x;
    __half2 a0 = ((const __half2*)g1)[i * 2 + 0];
    __half2 a1 = ((const __half2*)g1)[i * 2 + 1];
    __half2 c0 = ((const __half2*)g2)[i * 2 + 0];
    __half2 c1 = ((const __half2*)g2)[i * 2 + 1];
    float2 af0 = __half22float2(a0), af1 = __half22float2(a1);
    float2 cf0 = __half22float2(c0), cf1 = __half22float2(c1);
    ((__half2*)g1)[i * 2 + 0] =
        __floats2half2_rn(af0.x * gelu_t(cf0.x), af0.y * gelu_t(cf0.y));
    ((__half2*)g1)[i * 2 + 1] =
        __floats2half2_rn(af1.x * gelu_t(cf1.x), af1.y * gelu_t(cf1.y));
}

// ---------------------------------------------------------------------------
// Launch
// ---------------------------------------------------------------------------
extern "C" void kernel_launch(void* const* d_in, const int* in_sizes, int n_in,
                              void* d_out, int out_size)
{
    (void)in_sizes; (void)n_in; (void)out_size;
    const float* x     = (const float*)d_in[0];
    const float* ln1_s = (const float*)d_in[2];
    const float* ln1_b = (const float*)d_in[3];
    const float* Wq    = (const float*)d_in[4];
    const float* bq    = (const float*)d_in[5];
    const float* Wk    = (const float*)d_in[6];
    const float* bk    = (const float*)d_in[7];
    const float* Wv    = (const float*)d_in[8];
    const float* bv    = (const float*)d_in[9];
    const float* qn_s  = (const float*)d_in[10];
    const float* qn_b  = (const float*)d_in[11];
    const float* kn_s  = (const float*)d_in[12];
    const float* kn_b  = (const float*)d_in[13];
    const float* Wo    = (const float*)d_in[14];
    const float* bo    = (const float*)d_in[15];
    const float* ln2_s = (const float*)d_in[16];
    const float* ln2_b = (const float*)d_in[17];
    const float* W1    = (const float*)d_in[18];
    const float* b1    = (const float*)d_in[19];
    const float* W2    = (const float*)d_in[20];
    const float* b2    = (const float*)d_in[21];
    const float* W3    = (const float*)d_in[22];
    const float* b3    = (const float*)d_in[23];

    void *p_xn, *p_qkv, *p_res, *p_big, *p_wt, *p_vt, *p_bias;
    cudaGetSymbolAddress(&p_xn,   g_xn);
    cudaGetSymbolAddress(&p_qkv,  g_qkv);
    cudaGetSymbolAddress(&p_res,  g_res);
    cudaGetSymbolAddress(&p_big,  g_big);
    cudaGetSymbolAddress(&p_wt,   g_wt);
    cudaGetSymbolAddress(&p_vt,   g_vt);
    cudaGetSymbolAddress(&p_bias, g_bias);

    __half* xn  = (__half*)p_xn;
    __half* qkv = (__half*)p_qkv;
    __half* qh  = qkv;
    __half* kh  = qkv + (size_t)4194304;
    __half* vh  = qkv + (size_t)8388608;
    float*  res = (float*)p_res;
    __half* wt  = (__half*)p_wt;
    __half* vt  = (__half*)p_vt;
    __half* h1  = (__half*)p_big;
    __half* h2  = h1 + (size_t)16777216;
    float*  bsc = (float*)p_bias;
    float* out = (float*)d_out;

    cudaFuncSetAttribute(flash_h, cudaFuncAttributeMaxDynamicSharedMemorySize, FL_SMEM);
    cudaFuncSetAttribute(gemm_h<0>, cudaFuncAttributeMaxDynamicSharedMemorySize, GE_SMEM);
    cudaFuncSetAttribute(gemm_h<1>, cudaFuncAttributeMaxDynamicSharedMemorySize, GE_SMEM);

    const size_t MB1 = 1024 * 1024;
    __half* wqt = wt;                 // [3072][1024] concatenated q|k|v
    __half* wot = wt + 3 * MB1;
    __half* w1t = wt + 4 * MB1;       // [8192][1024] concatenated w1|w2
    __half* w3t = wt + 12 * MB1;

    // 0. weight transposes -> half, batched; bias concat
    trans_f2h4<<<dim3(32, 32, 4), 256>>>(Wq, Wk, Wv, Wo,
                                         wqt, wqt + 1 * MB1, wqt + 2 * MB1, wot, 1024, 1024);
    trans_f2h4<<<dim3(128, 32, 2), 256>>>(W1, W2, W1, W2,
                                          w1t, w1t + 4 * MB1, w1t, w1t + 4 * MB1, 1024, 4096);
    trans_f2h4<<<dim3(32, 128, 1), 256>>>(W3, W3, W3, W3, w3t, w3t, w3t, w3t, 4096, 1024);
    concat_bias<<<44, 256>>>(bsc, bq, bk, bv, b1, b2);

    // 1. LN1 -> xn (half)
    ln_kernel<<<4096, 256>>>(x, ln1_s, ln1_b, xn);

    // 2. fused QKV projection (M=4096, N=3072, K=1024) -> q|k|v segments
    gemm_h<0><<<dim3(24, 16), 256, GE_SMEM>>>(xn, wqt, bsc, nullptr, qkv,
                                              1024, 1024, 1024, 1024, 4194304);

    // 3-4. QK-norm
    qknorm_kernel<<<8192, 256>>>(qh, qn_s, qn_b);
    qknorm_kernel<<<8192, 256>>>(kh, kn_s, kn_b);

    // 5. v -> vt per batch
    trans_h2h<<<dim3(32, 32, 4), 256>>>(vh, vt, 1024, 1024);

    // 6. flash attention -> attn_out overwrites vh
    flash_h<<<dim3(8, 64), 256, FL_SMEM>>>(qh, kh, vt, vh);

    // 7. O projection + residual (f32 out)
    gemm_h<1><<<dim3(8, 16), 256, GE_SMEM>>>(vh, wot, bo, x, res, 1024, 1024, 1024, 0, 1024);

    // 8. LN2 -> xn (half)
    ln_kernel<<<4096, 256>>>(res, ln2_s, ln2_b, xn);

    // 9. fused FFN up (M=4096, N=8192, K=1024) -> h1 | h2
    gemm_h<0><<<dim3(64, 16), 256, GE_SMEM>>>(xn, w1t, bsc + 4096, nullptr, h1,
                                              1024, 1024, 1024, 4096, 16777216);

    // 10. GeGLU
    geglu_kernel<<<16384, 256>>>(h1, h2);

    // 11. Down projection + residual -> d_out (M=4096, N=1024, K=4096)
    gemm_h<1><<<dim3(8, 16), 256, GE_SMEM>>>(h1, w3t, b3, res, out, 4096, 4096, 4096, 0, 1024);
}

// round 10
// speedup vs baseline: 1.1103x; 1.1103x over previous
#include <cuda_runtime.h>
#include <cuda_fp16.h>
#include <math.h>
#include <stdint.h>

#define EPSF 1e-6f

// Problem constants: B=4, S=1024, D=1024, H=16, DH=64, F=4096, M=B*S=4096
__device__ float g_xn  [4096 * 1024 / 2];    // xn (half)
__device__ float g_qkv [6 * 1024 * 1024];    // q|k|v (half, 3 x 4M halves); v->attn_out
__device__ float g_res [4096 * 1024];        // residual after attention (f32)
__device__ float g_big [16 * 1024 * 1024];   // h1/h2 (half, 2 x 16M halves)
__device__ float g_wt  [8 * 1024 * 1024];    // transposed half weights (16M halves)
__device__ float g_vt  [2 * 1024 * 1024];    // vt (half) [b][d][s]
__device__ float g_bias[16384];              // b_qkv (3072) @0, b12 (8192) @4096

// ---------------------------------------------------------------------------
// Helpers
// ---------------------------------------------------------------------------
__device__ __forceinline__ void cp_async16(uint32_t dst, const void* src)
{
    asm volatile("cp.async.cg.shared.global [%0], [%1], 16;\n" :: "r"(dst), "l"(src));
}
__device__ __forceinline__ void cp_commit() { asm volatile("cp.async.commit_group;\n"); }
__device__ __forceinline__ void cp_wait0()  { asm volatile("cp.async.wait_group 0;\n"); }

__device__ __forceinline__ uint32_t smem_u32(const void* p)
{
    uint32_t a;
    asm("{ .reg .u64 t; cvta.to.shared.u64 t, %1; cvt.u32.u64 %0, t; }" : "=r"(a) : "l"(p));
    return a;
}
__device__ __forceinline__ void ldsm4(uint32_t& r0, uint32_t& r1, uint32_t& r2, uint32_t& r3,
                                      uint32_t a)
{
    asm volatile("ldmatrix.sync.aligned.m8n8.x4.shared.b16 {%0,%1,%2,%3}, [%4];"
                 : "=r"(r0), "=r"(r1), "=r"(r2), "=r"(r3) : "r"(a));
}
__device__ __forceinline__ void mma_h(float c[4], const uint32_t a[4], const uint32_t b[2])
{
    asm volatile(
        "mma.sync.aligned.m16n8k16.row.col.f32.f16.f16.f32 "
        "{%0,%1,%2,%3}, {%4,%5,%6,%7}, {%8,%9}, {%0,%1,%2,%3};\n"
        : "+f"(c[0]), "+f"(c[1]), "+f"(c[2]), "+f"(c[3])
        : "r"(a[0]), "r"(a[1]), "r"(a[2]), "r"(a[3]), "r"(b[0]), "r"(b[1]));
}

// ---------------------------------------------------------------------------
// fp16 tensor-core GEMM: round-8 shape (BM=128 BN=128, 8 warps, 64x32 warp
// tiles, double buffer, wait_group 0) with BK widened 32 -> 64.
// Smem row stride 72 halves (144 B) -> ldmatrix rows hit 8 distinct 16B
// segments mod 128B: conflict-free.
// MODE 0: half out, segmented columns (fused QKV / fused FFN).
// MODE 1: float out = acc + bias + Res (ldc = segStride).
// ---------------------------------------------------------------------------
#define GE_STAGE (128 * 72 * 2)                  // 18432 B per matrix per stage
#define GE_SMEM  (4 * GE_STAGE)                  // 73728 B

template <int MODE>
__global__ __launch_bounds__(256) void gemm_h(
    const __half* __restrict__ A, const __half* __restrict__ B,
    const float* __restrict__ bias, const float* __restrict__ Res,
    void* __restrict__ Cv, int K, int lda, int ldb, int segW, int segStride)
{
    extern __shared__ __half gsm[];
    const uint32_t sA = smem_u32(gsm);
    const uint32_t sB = sA + 2 * GE_STAGE;

    const int t    = threadIdx.x;
    const int lane = t & 31;
    const int warp = t >> 5;
    const size_t m0 = (size_t)blockIdx.y * 128;
    const size_t n0 = (size_t)blockIdx.x * 128;
    const int wm = (warp >> 2) * 64;
    const int wn = (warp & 3) * 32;

    // cp.async maps: 128 rows x 8 chunks of 16B per matrix -> 4 chunks/thread
    uint32_t dOff[4];
    const __half* aS[4];
    const __half* bS[4];
    #pragma unroll
    for (int i = 0; i < 4; i++) {
        const int idx = t + 256 * i;
        const int row = idx >> 3, c = idx & 7;
        dOff[i] = (uint32_t)(row * 72 + c * 8) * 2;
        aS[i] = A + (m0 + row) * lda + c * 8;
        bS[i] = B + (n0 + row) * ldb + c * 8;
    }

    const int lq = lane >> 3, lr = lane & 7;
    uint32_t aAddr[4], bAddr[2];
    #pragma unroll
    for (int mt = 0; mt < 4; mt++)
        aAddr[mt] = sA + (uint32_t)((wm + mt * 16 + ((lq & 1) << 3) + lr) * 72 + ((lq >> 1) << 3)) * 2;
    #pragma unroll
    for (int p = 0; p < 2; p++)
        bAddr[p] = sB + (uint32_t)((wn + p * 16 + ((lq >> 1) << 3) + lr) * 72 + ((lq & 1) << 3)) * 2;

    float acc[4][4][4];
    #pragma unroll
    for (int mt = 0; mt < 4; mt++)
        #pragma unroll
        for (int nt = 0; nt < 4; nt++)
            #pragma unroll
            for (int i = 0; i < 4; i++) acc[mt][nt][i] = 0.f;

    // preload stage 0
    #pragma unroll
    for (int i = 0; i < 4; i++) {
        cp_async16(sA + dOff[i], aS[i]);
        cp_async16(sB + dOff[i], bS[i]);
    }
    cp_commit();

    const int nIter = K >> 6;
    for (int it = 0; it < nIter; ++it) {
        cp_wait0();
        __syncthreads();
        const int buf = it & 1;
        if (it + 1 < nIter) {
            const int k0 = (it + 1) << 6;
            const uint32_t off = (buf ^ 1) * GE_STAGE;
            #pragma unroll
            for (int i = 0; i < 4; i++) {
                cp_async16(sA + off + dOff[i], aS[i] + k0);
                cp_async16(sB + off + dOff[i], bS[i] + k0);
            }
            cp_commit();
        }
        const uint32_t off = buf * GE_STAGE;
        #pragma unroll
        for (int ks = 0; ks < 4; ks++) {
            const uint32_t kB = ks * 32;   // 16 halves
            uint32_t af[4][4];
            #pragma unroll
            for (int mt = 0; mt < 4; mt++)
                ldsm4(af[mt][0], af[mt][1], af[mt][2], af[mt][3], aAddr[mt] + off + kB);
            uint32_t bf[4][2];
            #pragma unroll
            for (int p = 0; p < 2; p++)
                ldsm4(bf[2 * p][0], bf[2 * p][1], bf[2 * p + 1][0], bf[2 * p + 1][1],
                      bAddr[p] + off + kB);
            #pragma unroll
            for (int mt = 0; mt < 4; mt++)
                #pragma unroll
                for (int nt = 0; nt < 4; nt++)
                    mma_h(acc[mt][nt], af[mt], bf[nt]);
        }
        __syncthreads();
    }

    // Epilogue
    if (MODE == 0) {
        const int seg  = (int)(n0 / segW);
        const int ncol = (int)(n0 % segW);
        __half* Cb = (__half*)Cv + (size_t)seg * segStride + m0 * segW + ncol;
        #pragma unroll
        for (int mt = 0; mt < 4; mt++) {
            const int r0 = wm + mt * 16 + (lane >> 2);
            #pragma unroll
            for (int nt = 0; nt < 4; nt++) {
                const int c = wn + nt * 8 + (lane & 3) * 2;
                const float b0 = bias[n0 + c], b1 = bias[n0 + c + 1];
                *(__half2*)(Cb + (size_t)r0 * segW + c) =
                    __floats2half2_rn(acc[mt][nt][0] + b0, acc[mt][nt][1] + b1);
                *(__half2*)(Cb + (size_t)(r0 + 8) * segW + c) =
                    __floats2half2_rn(acc[mt][nt][2] + b0, acc[mt][nt][3] + b1);
            }
        }
    } else {
        const int ldc = segStride;
        float* Cb = (float*)Cv + m0 * ldc + n0;
        const float* Rb = Res + m0 * ldc + n0;
        #pragma unroll
        for (int mt = 0; mt < 4; mt++) {
            const int r0 = wm + mt * 16 + (lane >> 2);
            #pragma unroll
            for (int nt = 0; nt < 4; nt++) {
                const int c = wn + nt * 8 + (lane & 3) * 2;
                const float b0 = bias[n0 + c], b1 = bias[n0 + c + 1];
                float2 ra = *(const float2*)(Rb + (size_t)r0 * ldc + c);
                float2 rb = *(const float2*)(Rb + (size_t)(r0 + 8) * ldc + c);
                *(float2*)(Cb + (size_t)r0 * ldc + c) =
                    make_float2(acc[mt][nt][0] + b0 + ra.x, acc[mt][nt][1] + b1 + ra.y);
                *(float2*)(Cb + (size_t)(r0 + 8) * ldc + c) =
                    make_float2(acc[mt][nt][2] + b0 + rb.x, acc[mt][nt][3] + b1 + rb.y);
            }
        }
    }
}

// ---------------------------------------------------------------------------
// Bias concat: b_qkv = bq|bk|bv at g_bias[0..3072); b12 = b1|b2 at [4096..12288)
// ---------------------------------------------------------------------------
__global__ __launch_bounds__(256) void concat_bias(
    float* __restrict__ dst, const float* __restrict__ bq, const float* __restrict__ bk,
    const float* __restrict__ bv, const float* __restrict__ b1, const float* __restrict__ b2)
{
    const int i = blockIdx.x * 256 + threadIdx.x;
    if (i < 1024)       dst[i] = bq[i];
    else if (i < 2048)  dst[i] = bk[i - 1024];
    else if (i < 3072)  dst[i] = bv[i - 2048];
    else if (i < 3072 + 4096)  dst[1024 + i] = b1[i - 3072];
    else if (i < 3072 + 8192)  dst[1024 + i] = b2[i - 7168];
}

// ---------------------------------------------------------------------------
// Batched transpose f32 -> half: 4 independent sources, z selects source.
// ---------------------------------------------------------------------------
__global__ __launch_bounds__(256) void trans_f2h4(
    const float* __restrict__ i0, const float* __restrict__ i1,
    const float* __restrict__ i2, const float* __restrict__ i3,
    __half* __restrict__ o0, __half* __restrict__ o1,
    __half* __restrict__ o2, __half* __restrict__ o3, int R, int C)
{
    __shared__ float tile[32][33];
    const float* in;
    __half* out;
    switch (blockIdx.z) {
        case 0: in = i0; out = o0; break;
        case 1: in = i1; out = o1; break;
        case 2: in = i2; out = o2; break;
        default: in = i3; out = o3; break;
    }
    const int c0 = blockIdx.x * 32, r0 = blockIdx.y * 32;
    const int tx = threadIdx.x & 31, ty = threadIdx.x >> 5;
    #pragma unroll
    for (int i = 0; i < 4; i++)
        tile[ty + 8 * i][tx] = in[(size_t)(r0 + ty + 8 * i) * C + c0 + tx];
    __syncthreads();
    #pragma unroll
    for (int i = 0; i < 4; i++)
        out[(size_t)(c0 + ty + 8 * i) * R + r0 + tx] = __float2half_rn(tile[tx][ty + 8 * i]);
}

// ---------------------------------------------------------------------------
// Transpose half -> half (batched over z): in[R][C] -> out[C][R]
// ---------------------------------------------------------------------------
__global__ __launch_bounds__(256) void trans_h2h(
    const __half* __restrict__ in, __half* __restrict__ out, int R, int C)
{
    __shared__ __half tile[32][34];
    const size_t zoff = (size_t)blockIdx.z * R * C;
    in += zoff; out += zoff;
    const int c0 = blockIdx.x * 32, r0 = blockIdx.y * 32;
    const int tx = threadIdx.x & 31, ty = threadIdx.x >> 5;
    #pragma unroll
    for (int i = 0; i < 4; i++)
        tile[ty + 8 * i][tx] = in[(size_t)(r0 + ty + 8 * i) * C + c0 + tx];
    __syncthreads();
    #pragma unroll
    for (int i = 0; i < 4; i++)
        out[(size_t)(c0 + ty + 8 * i) * R + r0 + tx] = tile[tx][ty + 8 * i];
}

// ---------------------------------------------------------------------------
// Flash attention fp16 (proven round-6 version).
// ---------------------------------------------------------------------------
#define FL_SMEM ((128 * 72 + 64 * 136 + 128 * 136) * 2)

__global__ __launch_bounds__(256) void flash_h(
    const __half* __restrict__ q, const __half* __restrict__ k,
    const __half* __restrict__ vt, __half* __restrict__ out)
{
    extern __shared__ __half smh[];
    const uint32_t sK = smem_u32(smh);
    const uint32_t sV = sK + 128 * 72 * 2;
    const uint32_t sP = sV + 64 * 136 * 2;
    __half* sPh = smh + 128 * 72 + 64 * 136;

    const int t = threadIdx.x;
    const int lane = t & 31, warp = t >> 5;
    const int lq = lane >> 3, lr = lane & 7;
    const int bh = blockIdx.y, b = bh >> 4, h = bh & 15;
    const int q0 = blockIdx.x * 128;
    const int wm = warp * 16;

    const __half* qb = q + ((size_t)b * 1024 + q0) * 1024 + h * 64;
    const __half* kb = k + ((size_t)b << 20) + h * 64;
    const __half* vb = vt + ((size_t)b << 20) + (size_t)h * 64 * 1024;

    {
        #pragma unroll
        for (int i = 0; i < 4; i++) {
            const int idx = t + 256 * i;
            const int row = idx >> 3, c = idx & 7;
            cp_async16(sP + (uint32_t)(row * 72 + c * 8) * 2, qb + (size_t)row * 1024 + c * 8);
        }
    }
    cp_commit(); cp_wait0(); __syncthreads();

    uint32_t qf[4][4];
    {
        const uint32_t a0 = sP + (uint32_t)((wm + ((lq & 1) << 3) + lr) * 72 + ((lq >> 1) << 3)) * 2;
        #pragma unroll
        for (int ks = 0; ks < 4; ks++)
            ldsm4(qf[ks][0], qf[ks][1], qf[ks][2], qf[ks][3], a0 + ks * 32);
    }
    __syncthreads();

    float o[8][4];
    #pragma unroll
    for (int i = 0; i < 8; i++)
        #pragma unroll
        for (int j = 0; j < 4; j++) o[i][j] = 0.f;
    float m0 = -1e30f, m1 = -1e30f, l0 = 0.f, l1 = 0.f;

    const uint32_t aP = sP + (uint32_t)((wm + ((lq & 1) << 3) + lr) * 136 + ((lq >> 1) << 3)) * 2;

    for (int it = 0; it < 8; ++it) {
        const int kt0 = it * 128;
        #pragma unroll
        for (int i = 0; i < 4; i++) {
            const int idx = t + 256 * i;
            const int row = idx >> 3, c = idx & 7;
            cp_async16(sK + (uint32_t)(row * 72 + c * 8) * 2,
                       kb + (size_t)(kt0 + row) * 1024 + c * 8);
        }
        #pragma unroll
        for (int i = 0; i < 4; i++) {
            const int idx = t + 256 * i;
            const int row = idx >> 4, c = idx & 15;
            cp_async16(sV + (uint32_t)(row * 136 + c * 8) * 2,
                       vb + (size_t)row * 1024 + kt0 + c * 8);
        }
        cp_commit(); cp_wait0(); __syncthreads();

        float s[16][4];
        #pragma unroll
        for (int i = 0; i < 16; i++)
            #pragma unroll
            for (int j = 0; j < 4; j++) s[i][j] = 0.f;
        #pragma unroll
        for (int ks = 0; ks < 4; ks++) {
            uint32_t bf[16][2];
            #pragma unroll
            for (int p = 0; p < 8; p++) {
                const uint32_t addr =
                    sK + (uint32_t)((p * 16 + ((lq >> 1) << 3) + lr) * 72 + ((lq & 1) << 3)) * 2
                       + ks * 32;
                ldsm4(bf[2 * p][0], bf[2 * p][1], bf[2 * p + 1][0], bf[2 * p + 1][1], addr);
            }
            #pragma unroll
            for (int nt = 0; nt < 16; nt++)
                mma_h(s[nt], qf[ks], bf[nt]);
        }

        float c0v = -1e30f, c1v = -1e30f;
        #pragma unroll
        for (int nt = 0; nt < 16; nt++) {
            c0v = fmaxf(c0v, fmaxf(s[nt][0], s[nt][1]));
            c1v = fmaxf(c1v, fmaxf(s[nt][2], s[nt][3]));
        }
        c0v = fmaxf(c0v, __shfl_xor_sync(0xffffffffu, c0v, 1));
        c0v = fmaxf(c0v, __shfl_xor_sync(0xffffffffu, c0v, 2));
        c1v = fmaxf(c1v, __shfl_xor_sync(0xffffffffu, c1v, 1));
        c1v = fmaxf(c1v, __shfl_xor_sync(0xffffffffu, c1v, 2));
        const float m0n = fmaxf(m0, c0v * 0.125f);
        const float m1n = fmaxf(m1, c1v * 0.125f);
        const float cor0 = __expf(m0 - m0n);
        const float cor1 = __expf(m1 - m1n);
        m0 = m0n; m1 = m1n;
        float sum0 = 0.f, sum1 = 0.f;
        {
            __half* pr0 = sPh + (size_t)(wm + (lane >> 2)) * 136 + 2 * (lane & 3);
            __half* pr1 = pr0 + 8 * 136;
            #pragma unroll
            for (int nt = 0; nt < 16; nt++) {
                float p0 = __expf(fmaf(0.125f, s[nt][0], -m0n));
                float p1 = __expf(fmaf(0.125f, s[nt][1], -m0n));
                float p2 = __expf(fmaf(0.125f, s[nt][2], -m1n));
                float p3 = __expf(fmaf(0.125f, s[nt][3], -m1n));
                sum0 += p0 + p1; sum1 += p2 + p3;
                *(__half2*)(pr0 + nt * 8) = __floats2half2_rn(p0, p1);
                *(__half2*)(pr1 + nt * 8) = __floats2half2_rn(p2, p3);
            }
        }
        sum0 += __shfl_xor_sync(0xffffffffu, sum0, 1);
        sum0 += __shfl_xor_sync(0xffffffffu, sum0, 2);
        sum1 += __shfl_xor_sync(0xffffffffu, sum1, 1);
        sum1 += __shfl_xor_sync(0xffffffffu, sum1, 2);
        l0 = l0 * cor0 + sum0;
        l1 = l1 * cor1 + sum1;
        #pragma unroll
        for (int nt = 0; nt < 8; nt++) {
            o[nt][0] *= cor0; o[nt][1] *= cor0;
            o[nt][2] *= cor1; o[nt][3] *= cor1;
        }
        __syncwarp();

        #pragma unroll
        for (int ks2 = 0; ks2 < 8; ks2++) {
            uint32_t af[4];
            ldsm4(af[0], af[1], af[2], af[3], aP + ks2 * 32);
            uint32_t bf2[8][2];
            #pragma unroll
            for (int p = 0; p < 4; p++) {
                const uint32_t addr =
                    sV + (uint32_t)((p * 16 + ((lq >> 1) << 3) + lr) * 136 + ((lq & 1) << 3)) * 2
                       + ks2 * 32;
                ldsm4(bf2[2 * p][0], bf2[2 * p][1], bf2[2 * p + 1][0], bf2[2 * p + 1][1], addr);
            }
            #pragma unroll
            for (int nt = 0; nt < 8; nt++)
                mma_h(o[nt], af, bf2[nt]);
        }
        __syncthreads();
    }

    const float inv0 = 1.f / l0, inv1 = 1.f / l1;
    __half* ob = out + ((size_t)b * 1024 + q0 + wm + (lane >> 2)) * 1024 + h * 64 + 2 * (lane & 3);
    #pragma unroll
    for (int nt = 0; nt < 8; nt++) {
        *(__half2*)(ob + nt * 8) = __floats2half2_rn(o[nt][0] * inv0, o[nt][1] * inv0);
        *(__half2*)(ob + 8 * 1024 + nt * 8) = __floats2half2_rn(o[nt][2] * inv1, o[nt][3] * inv1);
    }
}

// ---------------------------------------------------------------------------
// LayerNorm over D=1024, f32 in -> half out.
// ---------------------------------------------------------------------------
__global__ __launch_bounds__(256) void ln_kernel(
    const float* __restrict__ in, const float* __restrict__ sc,
    const float* __restrict__ bi, __half* __restrict__ out)
{
    const int row = blockIdx.x;
    const int t = threadIdx.x;
    const float4* x4 = (const float4*)(in + (size_t)row * 1024);
    float4 v = x4[t];
    float s  = v.x + v.y + v.z + v.w;
    float ss = v.x * v.x + v.y * v.y + v.z * v.z + v.w * v.w;
    #pragma unroll
    for (int o = 16; o; o >>= 1) {
        s  += __shfl_xor_sync(0xffffffffu, s,  o);
        ss += __shfl_xor_sync(0xffffffffu, ss, o);
    }
    __shared__ float sred[8], ssred[8];
    if ((t & 31) == 0) { sred[t >> 5] = s; ssred[t >> 5] = ss; }
    __syncthreads();
    float tot = 0.f, tots = 0.f;
    #pragma unroll
    for (int w = 0; w < 8; w++) { tot += sred[w]; tots += ssred[w]; }
    const float mean = tot * (1.f / 1024.f);
    const float var  = tots * (1.f / 1024.f) - mean * mean;
    const float inv  = rsqrtf(var + EPSF);
    float4 sv = ((const float4*)sc)[t];
    float4 bv = ((const float4*)bi)[t];
    __half2* o2 = (__half2*)(out + (size_t)row * 1024);
    o2[t * 2 + 0] = __floats2half2_rn((v.x - mean) * inv * sv.x + bv.x,
                                      (v.y - mean) * inv * sv.y + bv.y);
    o2[t * 2 + 1] = __floats2half2_rn((v.z - mean) * inv * sv.z + bv.z,
                                      (v.w - mean) * inv * sv.w + bv.w);
}

// ---------------------------------------------------------------------------
// QK-norm over DH=64 with (H,DH) f32 scale/bias; half in-place.
// ---------------------------------------------------------------------------
__global__ __launch_bounds__(256) void qknorm_kernel(
    __half* __restrict__ q, const float* __restrict__ sc, const float* __restrict__ bi)
{
    const int gw   = (blockIdx.x * 256 + threadIdx.x) >> 5;
    const int lane = threadIdx.x & 31;
    const int h  = gw & 15;
    const int bs = gw >> 4;
    __half2* p = (__half2*)(q + (size_t)bs * 1024 + h * 64) + lane;
    float2 v = __half22float2(*p);
    float s  = v.x + v.y;
    float ss = v.x * v.x + v.y * v.y;
    #pragma unroll
    for (int o = 16; o; o >>= 1) {
        s  += __shfl_xor_sync(0xffffffffu, s,  o);
        ss += __shfl_xor_sync(0xffffffffu, ss, o);
    }
    const float mean = s * (1.f / 64.f);
    const float var  = ss * (1.f / 64.f) - mean * mean;
    const float inv  = rsqrtf(var + EPSF);
    const float* scp = sc + h * 64 + lane * 2;
    const float* bip = bi + h * 64 + lane * 2;
    *p = __floats2half2_rn((v.x - mean) * inv * scp[0] + bip[0],
                           (v.y - mean) * inv * scp[1] + bip[1]);
}

// ---------------------------------------------------------------------------
// GeGLU: h1 <- h1 * gelu_tanh(h2), half, 4 halves/thread.
// ---------------------------------------------------------------------------
__device__ __forceinline__ float gelu_t(float x)
{
    return 0.5f * x * (1.f + tanhf(0.7978845608028654f * (x + 0.044715f * x * x * x)));
}

__global__ __launch_bounds__(256) void geglu_kernel(
    __half* __restrict__ g1, const __half* __restrict__ g2)
{
    const size_t i = (size_t)blockIdx.x * 256 + threadIdx.x;
    __half2 a0 = ((const __half2*)g1)[i * 2 + 0];
    __half2 a1 = ((const __half2*)g1)[i * 2 + 1];
    __half2 c0 = ((const __half2*)g2)[i * 2 + 0];
    __half2 c1 = ((const __half2*)g2)[i * 2 + 1];
    float2 af0 = __half22float2(a0), af1 = __half22float2(a1);
    float2 cf0 = __half22float2(c0), cf1 = __half22float2(c1);
    ((__half2*)g1)[i * 2 + 0] =
        __floats2half2_rn(af0.x * gelu_t(cf0.x), af0.y * gelu_t(cf0.y));
    ((__half2*)g1)[i * 2 + 1] =
        __floats2half2_rn(af1.x * gelu_t(cf1.x), af1.y * gelu_t(cf1.y));
}

// ---------------------------------------------------------------------------
// Launch
// ---------------------------------------------------------------------------
extern "C" void kernel_launch(void* const* d_in, const int* in_sizes, int n_in,
                              void* d_out, int out_size)
{
    (void)in_sizes; (void)n_in; (void)out_size;
    const float* x     = (const float*)d_in[0];
    const float* ln1_s = (const float*)d_in[2];
    const float* ln1_b = (const float*)d_in[3];
    const float* Wq    = (const float*)d_in[4];
    const float* bq    = (const float*)d_in[5];
    const float* Wk    = (const float*)d_in[6];
    const float* bk    = (const float*)d_in[7];
    const float* Wv    = (const float*)d_in[8];
    const float* bv    = (const float*)d_in[9];
    const float* qn_s  = (const float*)d_in[10];
    const float* qn_b  = (const float*)d_in[11];
    const float* kn_s  = (const float*)d_in[12];
    const float* kn_b  = (const float*)d_in[13];
    const float* Wo    = (const float*)d_in[14];
    const float* bo    = (const float*)d_in[15];
    const float* ln2_s = (const float*)d_in[16];
    const float* ln2_b = (const float*)d_in[17];
    const float* W1    = (const float*)d_in[18];
    const float* b1    = (const float*)d_in[19];
    const float* W2    = (const float*)d_in[20];
    const float* b2    = (const float*)d_in[21];
    const float* W3    = (const float*)d_in[22];
    const float* b3    = (const float*)d_in[23];

    void *p_xn, *p_qkv, *p_res, *p_big, *p_wt, *p_vt, *p_bias;
    cudaGetSymbolAddress(&p_xn,   g_xn);
    cudaGetSymbolAddress(&p_qkv,  g_qkv);
    cudaGetSymbolAddress(&p_res,  g_res);
    cudaGetSymbolAddress(&p_big,  g_big);
    cudaGetSymbolAddress(&p_wt,   g_wt);
    cudaGetSymbolAddress(&p_vt,   g_vt);
    cudaGetSymbolAddress(&p_bias, g_bias);

    __half* xn  = (__half*)p_xn;
    __half* qkv = (__half*)p_qkv;
    __half* qh  = qkv;
    __half* kh  = qkv + (size_t)4194304;
    __half* vh  = qkv + (size_t)8388608;
    float*  res = (float*)p_res;
    __half* wt  = (__half*)p_wt;
    __half* vt  = (__half*)p_vt;
    __half* h1  = (__half*)p_big;
    __half* h2  = h1 + (size_t)16777216;
    float*  bsc = (float*)p_bias;
    float* out = (float*)d_out;

    cudaFuncSetAttribute(flash_h, cudaFuncAttributeMaxDynamicSharedMemorySize, FL_SMEM);
    cudaFuncSetAttribute(gemm_h<0>, cudaFuncAttributeMaxDynamicSharedMemorySize, GE_SMEM);
    cudaFuncSetAttribute(gemm_h<1>, cudaFuncAttributeMaxDynamicSharedMemorySize, GE_SMEM);

    const size_t MB1 = 1024 * 1024;
    __half* wqt = wt;                 // [3072][1024] concatenated q|k|v
    __half* wot = wt + 3 * MB1;
    __half* w1t = wt + 4 * MB1;       // [8192][1024] concatenated w1|w2
    __half* w3t = wt + 12 * MB1;

    // 0. weight transposes -> half, batched; bias concat
    trans_f2h4<<<dim3(32, 32, 4), 256>>>(Wq, Wk, Wv, Wo,
                                         wqt, wqt + 1 * MB1, wqt + 2 * MB1, wot, 1024, 1024);
    trans_f2h4<<<dim3(128, 32, 2), 256>>>(W1, W2, W1, W2,
                                          w1t, w1t + 4 * MB1, w1t, w1t + 4 * MB1, 1024, 4096);
    trans_f2h4<<<dim3(32, 128, 1), 256>>>(W3, W3, W3, W3, w3t, w3t, w3t, w3t, 4096, 1024);
    concat_bias<<<44, 256>>>(bsc, bq, bk, bv, b1, b2);

    // 1. LN1 -> xn (half)
    ln_kernel<<<4096, 256>>>(x, ln1_s, ln1_b, xn);

    // 2. fused QKV projection (M=4096, N=3072, K=1024) -> q|k|v segments
    gemm_h<0><<<dim3(24, 32), 256, GE_SMEM>>>(xn, wqt, bsc, nullptr, qkv,
                                              1024, 1024, 1024, 1024, 4194304);

    // 3-4. QK-norm
    qknorm_kernel<<<8192, 256>>>(qh, qn_s, qn_b);
    qknorm_kernel<<<8192, 256>>>(kh, kn_s, kn_b);

    // 5. v -> vt per batch
    trans_h2h<<<dim3(32, 32, 4), 256>>>(vh, vt, 1024, 1024);

    // 6. flash attention -> attn_out overwrites vh
    flash_h<<<dim3(8, 64), 256, FL_SMEM>>>(qh, kh, vt, vh);

    // 7. O projection + residual (f32 out)
    gemm_h<1><<<dim3(8, 32), 256, GE_SMEM>>>(vh, wot, bo, x, res, 1024, 1024, 1024, 0, 1024);

    // 8. LN2 -> xn (half)
    ln_kernel<<<4096, 256>>>(res, ln2_s, ln2_b, xn);

    // 9. fused FFN up (M=4096, N=8192, K=1024) -> h1 | h2
    gemm_h<0><<<dim3(64, 32), 256, GE_SMEM>>>(xn, w1t, bsc + 4096, nullptr, h1,
                                              1024, 1024, 1024, 4096, 16777216);

    // 10. GeGLU
    geglu_kernel<<<16384, 256>>>(h1, h2);

    // 11. Down projection + residual -> d_out (M=4096, N=1024, K=4096)
    gemm_h<1><<<dim3(8, 32), 256, GE_SMEM>>>(h1, w3t, b3, res, out, 4096, 4096, 4096, 0, 1024);
}